// round 9
// baseline (speedup 1.0000x reference)
#include <cuda_runtime.h>
#include <cuda_fp16.h>
#include <math.h>

#define NMAX 50000
#define EMAX 800000
#define C 256

typedef unsigned long long u64;
typedef unsigned int u32;

// ---------------- scratch (static device globals; no allocation) ----------------
__device__ int   g_src[EMAX];
__device__ int   g_dst[EMAX];
__device__ int   g_cnt[NMAX];
__device__ int   g_rowstart[NMAX + 1];
__device__ int   g_cursor[NMAX];
__device__ int   g_csr[EMAX];
__device__ __align__(16) float g_pq[NMAX * 4];
__device__ int   g_is64;
__device__ int   g_blocksums[64];
__device__ __align__(16) __half g_Whalf[256 * 512];        // [W1l|W1r] fp16
__device__ __align__(16) float4 g_W2pack[256];             // {W2l0,W2l1,W2r0,W2r1}[col]
__device__ __align__(16) __half g_xhalf[(size_t)NMAX * C];

__device__ __forceinline__ u32 packhf(float a, float b) {
    __half2 h = __floats2half2_rn(a, b);
    return *(u32*)&h;
}
__device__ __forceinline__ void mma16816(float* d, const u32* a, const u32* b) {
    asm volatile(
        "mma.sync.aligned.m16n8k16.row.col.f32.f16.f16.f32 "
        "{%0,%1,%2,%3}, {%4,%5,%6,%7}, {%8,%9}, {%0,%1,%2,%3};"
        : "+f"(d[0]), "+f"(d[1]), "+f"(d[2]), "+f"(d[3])
        : "r"(a[0]), "r"(a[1]), "r"(a[2]), "r"(a[3]), "r"(b[0]), "r"(b[1]));
}
__device__ __forceinline__ u32 smem_u32(const void* p) {
    u32 a;
    asm("{ .reg .u64 t; cvta.to.shared.u64 t, %1; cvt.u32.u64 %0, t; }" : "=r"(a) : "l"(p));
    return a;
}
#define CP16(dst, src, sz) \
    asm volatile("cp.async.cg.shared.global [%0], [%1], 16, %2;" \
                 :: "r"(dst), "l"(src), "r"(sz))
#define CP_COMMIT() asm volatile("cp.async.commit_group;")
#define CP_WAIT(n)  asm volatile("cp.async.wait_group %0;" :: "n"(n))

// ---------------- init: zero counts + dtype detection ----------------
__global__ void init_kernel(const unsigned* __restrict__ w, int n) {
    int i = blockIdx.x * blockDim.x + threadIdx.x;
    if (i < n) g_cnt[i] = 0;
    if (blockIdx.x == 0) {
        __shared__ int nz;
        if (threadIdx.x == 0) nz = 0;
        __syncthreads();
        if (w[2 * threadIdx.x + 1] != 0u) atomicAdd(&nz, 1);
        __syncthreads();
        if (threadIdx.x == 0) g_is64 = (nz == 0) ? 1 : 0;
    }
}

// ---------------- merged prep: x->fp16 | edge convert+count | W->fp16 ----------------
__global__ void prep_kernel(const float* __restrict__ x, const int* __restrict__ ei,
                            const float* __restrict__ W1l, const float* __restrict__ W1r,
                            const float* __restrict__ W2l, const float* __restrict__ W2r,
                            int n, int E, int nbx, int nbc) {
    int b = blockIdx.x;
    int tid = threadIdx.x;
    if (b < nbx) {
        int idx = b * 256 + tid;
        if (idx < n * 64) {
            float4 v = *(const float4*)(x + (size_t)idx * 4);
            *(uint2*)(g_xhalf + (size_t)idx * 4) =
                make_uint2(packhf(v.x, v.y), packhf(v.z, v.w));
        }
    } else if (b < nbx + nbc) {
        int e = (b - nbx) * 256 + tid;
        if (e < E) {
            int s, d;
            if (g_is64) {
                const long long* p = (const long long*)ei;
                s = (int)p[e];
                d = (int)p[(size_t)E + e];
            } else {
                s = ei[e];
                d = ei[E + e];
            }
            if ((unsigned)s >= (unsigned)n) s = 0;
            if ((unsigned)d >= (unsigned)n) d = 0;
            g_src[e] = s;
            g_dst[e] = d;
            atomicAdd(&g_cnt[d], 1);
        }
    } else {
        int idx = (b - nbx - nbc) * 256 + tid;   // < 131072
        int nrow = idx >> 9;
        int k = idx & 511;
        float w = (k < 256) ? W1l[nrow * 256 + k] : W1r[nrow * 256 + (k - 256)];
        g_Whalf[idx] = __float2half_rn(w);
        if (idx < 256)
            g_W2pack[idx] = make_float4(W2l[idx], W2l[256 + idx], W2r[idx], W2r[256 + idx]);
    }
}

// ---------------- parallel exclusive scan (2 kernels) ----------------
__global__ void scan_block_kernel(int n) {
    int i = blockIdx.x * 1024 + threadIdx.x;
    int v = (i < n) ? g_cnt[i] : 0;
    int lane = threadIdx.x & 31, wid = threadIdx.x >> 5;
    int x = v;
    #pragma unroll
    for (int off = 1; off < 32; off <<= 1) {
        int t = __shfl_up_sync(0xffffffffu, x, off);
        if (lane >= off) x += t;
    }
    __shared__ int wsum[32];
    if (lane == 31) wsum[wid] = x;
    __syncthreads();
    if (wid == 0) {
        int s = wsum[lane];
        #pragma unroll
        for (int off = 1; off < 32; off <<= 1) {
            int t = __shfl_up_sync(0xffffffffu, s, off);
            if (lane >= off) s += t;
        }
        wsum[lane] = s;
    }
    __syncthreads();
    int incl = x + (wid > 0 ? wsum[wid - 1] : 0);
    if (i < n) g_rowstart[i] = incl - v;
    if (threadIdx.x == 1023) g_blocksums[blockIdx.x] = incl;
}

__global__ void scan_add_kernel(int n, int nb) {
    __shared__ int s_off;
    int b = blockIdx.x;
    if (threadIdx.x < 32) {
        int lane = threadIdx.x;
        int v = 0;
        if (lane < nb && lane < b) v += g_blocksums[lane];
        int l2 = lane + 32;
        if (l2 < nb && l2 < b) v += g_blocksums[l2];
        #pragma unroll
        for (int off = 16; off; off >>= 1)
            v += __shfl_xor_sync(0xffffffffu, v, off);
        if (lane == 0) s_off = v;
    }
    __syncthreads();
    int i = b * 1024 + threadIdx.x;
    if (i < n) {
        int r = g_rowstart[i] + s_off;
        g_rowstart[i] = r;
        g_cursor[i] = r;
    }
    if (b == nb - 1 && threadIdx.x == 0)
        g_rowstart[n] = s_off + g_blocksums[b];
}

__global__ void fill_kernel(int E) {
    int e = blockIdx.x * blockDim.x + threadIdx.x;
    if (e >= E) return;
    int pos = atomicAdd(&g_cursor[g_dst[e]], 1);
    g_csr[pos] = g_src[e];
}

// ---------------- fused aggregate + fp16 GEMM + pq epilogue ----------------
// CTA: 128 rows x 256 cols, 512 threads, warp grid 4m x 4n, warp tile 32x64.
// Phase 0: warp-per-8-nodes mean aggregation from g_xhalf -> smem A_AGG (fp16).
// Phase 1: D = [agg|x] @ W^T, A from A_AGG (kt<8) / cp.async x (kt>=8),
//          B (fp16 weights) double-buffered cp.async. fp32 accum.
#define PAA 528                      // A_AGG pitch bytes (264 halfs)
#define A_AGG 0                      // 128*528 = 67584
#define ASTG  67584                  // 2 x 128*80 = 20480
#define BSTG  88064                  // 2 x 256*80 = 40960
#define SW2   129024                 // 4096
#define SB1   133120                 // 1024
#define SMEMT 134144
#define PA 40                        // stage pitch in halfs (80 bytes)

__global__ void __launch_bounds__(512, 1) gemm_fused_kernel(
    const float* __restrict__ b1, const float* __restrict__ b2, int M)
{
    extern __shared__ __align__(16) char smem[];
    u32 sb = smem_u32(smem);
    int tid = threadIdx.x;
    int lane = tid & 31, wid = tid >> 5;
    int wm = wid >> 2, wn = wid & 3;
    int m0 = blockIdx.x * 128;

    float4* s_w2 = (float4*)(smem + SW2);
    float*  s_b1 = (float*)(smem + SB1);
    if (tid < 256) {
        s_w2[tid] = g_W2pack[tid];
        s_b1[tid] = b1[tid];
    }

    // B cp.async assignment: 1024 chunks of 16B per stage, 2 per thread
    // A cp.async assignment (x half): 512 chunks, 1 per thread
    int arow = tid >> 2, ach = tid & 3;
    int am = m0 + arow;
    u32 asz = (am < M) ? 16u : 0u;
    u32 a_soff = (u32)(arow * 80 + ach * 16);
    size_t a_goff = (size_t)am * C + ach * 8;

    auto issue = [&](int kt, int st) {
        if (kt >= 8)
            CP16(sb + ASTG + st * 10240 + a_soff,
                 g_xhalf + a_goff + (size_t)(kt - 8) * 32, asz);
        int kg = kt * 32;
        u32 s0 = sb + BSTG + st * 20480;
        #pragma unroll
        for (int i = 0; i < 2; i++) {
            int t = tid + i * 512;
            int nr = t >> 2, ch = t & 3;
            CP16(s0 + (u32)(nr * 80 + ch * 16),
                 g_Whalf + (size_t)nr * 512 + kg + ch * 8, 16u);
        }
        CP_COMMIT();
    };

    // prologue: B(0) load overlaps the aggregation phase
    issue(0, 0);

    // ---- phase 0: aggregate this CTA's 128 nodes into A_AGG (fp16) ----
    #pragma unroll 1
    for (int i = 0; i < 8; i++) {
        int row = wid * 8 + i;
        int node = m0 + row;
        float f0 = 0.f, f1 = 0.f, f2 = 0.f, f3 = 0.f;
        float f4 = 0.f, f5 = 0.f, f6 = 0.f, f7 = 0.f;
        if (node < M) {
            int e0 = g_rowstart[node], e1 = g_rowstart[node + 1];
            int e = e0;
            uint4 v = make_uint4(0, 0, 0, 0);
            if (e < e1)
                v = *(const uint4*)(g_xhalf + (size_t)g_csr[e] * C + 8 * lane);
            while (e < e1) {
                uint4 cur = v;
                int en = e + 1;
                if (en < e1)
                    v = *(const uint4*)(g_xhalf + (size_t)g_csr[en] * C + 8 * lane);
                float2 p0 = __half22float2(*(__half2*)&cur.x);
                float2 p1 = __half22float2(*(__half2*)&cur.y);
                float2 p2 = __half22float2(*(__half2*)&cur.z);
                float2 p3 = __half22float2(*(__half2*)&cur.w);
                f0 += p0.x; f1 += p0.y; f2 += p1.x; f3 += p1.y;
                f4 += p2.x; f5 += p2.y; f6 += p3.x; f7 += p3.y;
                e = en;
            }
            float inv = (e1 > e0) ? 1.f / (float)(e1 - e0) : 0.f;
            f0 *= inv; f1 *= inv; f2 *= inv; f3 *= inv;
            f4 *= inv; f5 *= inv; f6 *= inv; f7 *= inv;
        }
        *(uint4*)(smem + A_AGG + row * PAA + lane * 16) =
            make_uint4(packhf(f0, f1), packhf(f2, f3), packhf(f4, f5), packhf(f6, f7));
    }
    __syncthreads();

    // ---- phase 1: GEMM mainloop ----
    float c[2][8][4];
    #pragma unroll
    for (int mi = 0; mi < 2; mi++)
        #pragma unroll
        for (int ni = 0; ni < 8; ni++)
            #pragma unroll
            for (int j = 0; j < 4; j++) c[mi][ni][j] = 0.f;

    int ra = lane >> 2;
    int ka2 = (lane & 3) * 2;

    for (int kt = 0; kt < 16; kt++) {
        if (kt < 15) { issue(kt + 1, (kt + 1) & 1); CP_WAIT(1); }
        else         { CP_WAIT(0); }
        __syncthreads();
        const char* abase;
        int apitch;
        if (kt < 8) { abase = smem + A_AGG + kt * 64; apitch = PAA; }
        else        { abase = smem + ASTG + (kt & 1) * 10240; apitch = 80; }
        const char* bbase = smem + BSTG + (kt & 1) * 20480;
        #pragma unroll
        for (int k16 = 0; k16 < 2; k16++) {
            int k0 = k16 * 16;
            u32 a[2][4];
            #pragma unroll
            for (int mi = 0; mi < 2; mi++) {
                const char* p = abase + (32 * wm + 16 * mi + ra) * apitch + (k0 + ka2) * 2;
                a[mi][0] = *(u32*)(p);
                a[mi][1] = *(u32*)(p + 8 * apitch);
                a[mi][2] = *(u32*)(p + 16);
                a[mi][3] = *(u32*)(p + 8 * apitch + 16);
            }
            u32 bh[8][2];
            #pragma unroll
            for (int ni = 0; ni < 8; ni++) {
                const char* p = bbase + (64 * wn + 8 * ni + ra) * 80 + (k0 + ka2) * 2;
                bh[ni][0] = *(u32*)(p);
                bh[ni][1] = *(u32*)(p + 16);
            }
            #pragma unroll
            for (int mi = 0; mi < 2; mi++)
                #pragma unroll
                for (int ni = 0; ni < 8; ni++)
                    mma16816(c[mi][ni], a[mi], bh[ni]);
        }
        __syncthreads();
    }

    // ---- epilogue: h = relu(acc + b1); fused p,q projection ----
    float pp[2][2][4];
    #pragma unroll
    for (int mi = 0; mi < 2; mi++)
        #pragma unroll
        for (int hh = 0; hh < 2; hh++)
            #pragma unroll
            for (int r = 0; r < 4; r++) pp[mi][hh][r] = 0.f;
    #pragma unroll
    for (int mi = 0; mi < 2; mi++)
        #pragma unroll
        for (int ni = 0; ni < 8; ni++)
            #pragma unroll
            for (int j = 0; j < 4; j++) {
                int col = 64 * wn + 8 * ni + ka2 + (j & 1);
                float h = fmaxf(c[mi][ni][j] + s_b1[col], 0.f);
                float4 wv = s_w2[col];
                int hh = j >> 1;
                pp[mi][hh][0] = fmaf(h, wv.x, pp[mi][hh][0]);
                pp[mi][hh][1] = fmaf(h, wv.y, pp[mi][hh][1]);
                pp[mi][hh][2] = fmaf(h, wv.z, pp[mi][hh][2]);
                pp[mi][hh][3] = fmaf(h, wv.w, pp[mi][hh][3]);
            }
    #pragma unroll
    for (int mi = 0; mi < 2; mi++)
        #pragma unroll
        for (int hh = 0; hh < 2; hh++)
            #pragma unroll
            for (int r = 0; r < 4; r++) {
                float v = pp[mi][hh][r];
                v += __shfl_xor_sync(0xffffffffu, v, 1);
                v += __shfl_xor_sync(0xffffffffu, v, 2);
                pp[mi][hh][r] = v;
            }
    float* s_part = (float*)smem;   // [4 wn][128 row][4] — reuses A_AGG region
    if ((lane & 3) == 0) {
        #pragma unroll
        for (int mi = 0; mi < 2; mi++)
            #pragma unroll
            for (int hh = 0; hh < 2; hh++) {
                int row = 32 * wm + 16 * mi + 8 * hh + ra;
                *(float4*)&s_part[(wn * 128 + row) * 4] =
                    make_float4(pp[mi][hh][0], pp[mi][hh][1], pp[mi][hh][2], pp[mi][hh][3]);
            }
    }
    __syncthreads();
    if (tid < 128) {
        int m = m0 + tid;
        if (m < M) {
            float4 s = make_float4(0.f, 0.f, 0.f, 0.f);
            #pragma unroll
            for (int w = 0; w < 4; w++) {
                float4 v = *(float4*)&s_part[(w * 128 + tid) * 4];
                s.x += v.x; s.y += v.y; s.z += v.z; s.w += v.w;
            }
            *(float4*)&g_pq[m * 4] = make_float4(s.x, s.y, s.z + b2[0], s.w + b2[1]);
        }
    }
}

// ---------------- layer-2 aggregation + log_softmax ----------------
__global__ void final_kernel(float* __restrict__ out, int n) {
    int i = blockIdx.x * blockDim.x + threadIdx.x;
    if (i >= n) return;
    int s0 = g_rowstart[i], s1 = g_rowstart[i + 1];
    float p0 = 0.f, p1 = 0.f;
    for (int e = s0; e < s1; e++) {
        int s = g_csr[e];
        p0 += g_pq[s * 4 + 0];
        p1 += g_pq[s * 4 + 1];
    }
    float inv = (s1 > s0) ? 1.f / (float)(s1 - s0) : 0.f;
    float o0 = p0 * inv + g_pq[i * 4 + 2];
    float o1 = p1 * inv + g_pq[i * 4 + 3];
    float m = fmaxf(o0, o1);
    float l = m + log1pf(expf(fminf(o0, o1) - m));
    out[i * 2 + 0] = o0 - l;
    out[i * 2 + 1] = o1 - l;
}

// ---------------- launcher ----------------
extern "C" void kernel_launch(void* const* d_in, const int* in_sizes, int n_in,
                              void* d_out, int out_size) {
    const float* x   = (const float*)d_in[0];
    const int*   ei  = (const int*)d_in[1];
    const float* W1l = (const float*)d_in[2];
    const float* b1  = (const float*)d_in[3];
    const float* W1r = (const float*)d_in[4];
    const float* W2l = (const float*)d_in[5];
    const float* b2  = (const float*)d_in[6];
    const float* W2r = (const float*)d_in[7];
    float* out = (float*)d_out;

    int n = in_sizes[0] / C;  if (n > NMAX) n = NMAX;
    int E = in_sizes[1] / 2;  if (E > EMAX) E = EMAX;
    int nb = (n + 1023) / 1024;
    int nbx = (n * 64 + 255) / 256;
    int nbc = (E + 255) / 256;

    cudaFuncSetAttribute(gemm_fused_kernel, cudaFuncAttributeMaxDynamicSharedMemorySize,
                         SMEMT);

    init_kernel<<<(n + 255) / 256, 256>>>((const unsigned*)ei, n);
    prep_kernel<<<nbx + nbc + 512, 256>>>(x, ei, W1l, W1r, W2l, W2r, n, E, nbx, nbc);
    scan_block_kernel<<<nb, 1024>>>(n);
    scan_add_kernel<<<nb, 1024>>>(n, nb);
    fill_kernel<<<(E + 255) / 256, 256>>>(E);
    gemm_fused_kernel<<<(n + 127) / 128, 512, SMEMT>>>(b1, b2, n);
    final_kernel<<<(n + 255) / 256, 256>>>(out, n);
}

// round 10
// speedup vs baseline: 1.3459x; 1.3459x over previous
#include <cuda_runtime.h>
#include <cuda_fp16.h>
#include <math.h>

#define NMAX 50000
#define EMAX 800000
#define C 256

typedef unsigned long long u64;
typedef unsigned int u32;

// ---------------- scratch (static device globals; no allocation) ----------------
__device__ int   g_src[EMAX];
__device__ int   g_dst[EMAX];
__device__ int   g_cnt[NMAX];
__device__ int   g_rowstart[NMAX + 1];
__device__ int   g_cursor[NMAX];
__device__ int   g_csr[EMAX];
__device__ __align__(16) float g_pq[NMAX * 4];
__device__ int   g_is64;
__device__ int   g_blocksums[64];
__device__ __align__(16) __half g_Whalf[256 * 512];        // [W1l|W1r] fp16
__device__ __align__(16) float4 g_W2pack[256];             // {W2l0,W2l1,W2r0,W2r1}[col]
__device__ __align__(16) __half g_agghalf[(size_t)NMAX * C];
__device__ __align__(16) __half g_xhalf[(size_t)NMAX * C];

__device__ __forceinline__ u32 packhf(float a, float b) {
    __half2 h = __floats2half2_rn(a, b);
    return *(u32*)&h;
}
__device__ __forceinline__ void mma16816(float* d, const u32* a, const u32* b) {
    asm volatile(
        "mma.sync.aligned.m16n8k16.row.col.f32.f16.f16.f32 "
        "{%0,%1,%2,%3}, {%4,%5,%6,%7}, {%8,%9}, {%0,%1,%2,%3};"
        : "+f"(d[0]), "+f"(d[1]), "+f"(d[2]), "+f"(d[3])
        : "r"(a[0]), "r"(a[1]), "r"(a[2]), "r"(a[3]), "r"(b[0]), "r"(b[1]));
}
__device__ __forceinline__ u32 smem_u32(const void* p) {
    u32 a;
    asm("{ .reg .u64 t; cvta.to.shared.u64 t, %1; cvt.u32.u64 %0, t; }" : "=r"(a) : "l"(p));
    return a;
}
#define CP16(dst, src, sz) \
    asm volatile("cp.async.cg.shared.global [%0], [%1], 16, %2;" \
                 :: "r"(dst), "l"(src), "r"(sz))
#define CP_COMMIT() asm volatile("cp.async.commit_group;")
#define CP_WAIT(n)  asm volatile("cp.async.wait_group %0;" :: "n"(n))

// ---------------- init: zero counts + dtype detection ----------------
__global__ void init_kernel(const unsigned* __restrict__ w, int n) {
    int i = blockIdx.x * blockDim.x + threadIdx.x;
    if (i < n) g_cnt[i] = 0;
    if (blockIdx.x == 0) {
        __shared__ int nz;
        if (threadIdx.x == 0) nz = 0;
        __syncthreads();
        if (w[2 * threadIdx.x + 1] != 0u) atomicAdd(&nz, 1);
        __syncthreads();
        if (threadIdx.x == 0) g_is64 = (nz == 0) ? 1 : 0;
    }
}

// ---------------- merged prep: x->fp16 | edge convert+count | W->fp16 ----------------
__global__ void prep_kernel(const float* __restrict__ x, const int* __restrict__ ei,
                            const float* __restrict__ W1l, const float* __restrict__ W1r,
                            const float* __restrict__ W2l, const float* __restrict__ W2r,
                            int n, int E, int nbx, int nbc) {
    int b = blockIdx.x;
    int tid = threadIdx.x;
    if (b < nbx) {
        int idx = b * 256 + tid;
        if (idx < n * 64) {
            float4 v = *(const float4*)(x + (size_t)idx * 4);
            *(uint2*)(g_xhalf + (size_t)idx * 4) =
                make_uint2(packhf(v.x, v.y), packhf(v.z, v.w));
        }
    } else if (b < nbx + nbc) {
        int e = (b - nbx) * 256 + tid;
        if (e < E) {
            int s, d;
            if (g_is64) {
                const long long* p = (const long long*)ei;
                s = (int)p[e];
                d = (int)p[(size_t)E + e];
            } else {
                s = ei[e];
                d = ei[E + e];
            }
            if ((unsigned)s >= (unsigned)n) s = 0;
            if ((unsigned)d >= (unsigned)n) d = 0;
            g_src[e] = s;
            g_dst[e] = d;
            atomicAdd(&g_cnt[d], 1);
        }
    } else {
        int idx = (b - nbx - nbc) * 256 + tid;   // < 131072
        int nrow = idx >> 9;
        int k = idx & 511;
        float w = (k < 256) ? W1l[nrow * 256 + k] : W1r[nrow * 256 + (k - 256)];
        g_Whalf[idx] = __float2half_rn(w);
        if (idx < 256)
            g_W2pack[idx] = make_float4(W2l[idx], W2l[256 + idx], W2r[idx], W2r[256 + idx]);
    }
}

// ---------------- parallel exclusive scan (2 kernels) ----------------
__global__ void scan_block_kernel(int n) {
    int i = blockIdx.x * 1024 + threadIdx.x;
    int v = (i < n) ? g_cnt[i] : 0;
    int lane = threadIdx.x & 31, wid = threadIdx.x >> 5;
    int x = v;
    #pragma unroll
    for (int off = 1; off < 32; off <<= 1) {
        int t = __shfl_up_sync(0xffffffffu, x, off);
        if (lane >= off) x += t;
    }
    __shared__ int wsum[32];
    if (lane == 31) wsum[wid] = x;
    __syncthreads();
    if (wid == 0) {
        int s = wsum[lane];
        #pragma unroll
        for (int off = 1; off < 32; off <<= 1) {
            int t = __shfl_up_sync(0xffffffffu, s, off);
            if (lane >= off) s += t;
        }
        wsum[lane] = s;
    }
    __syncthreads();
    int incl = x + (wid > 0 ? wsum[wid - 1] : 0);
    if (i < n) g_rowstart[i] = incl - v;
    if (threadIdx.x == 1023) g_blocksums[blockIdx.x] = incl;
}

__global__ void scan_add_kernel(int n, int nb) {
    __shared__ int s_off;
    int b = blockIdx.x;
    if (threadIdx.x < 32) {
        int lane = threadIdx.x;
        int v = 0;
        if (lane < nb && lane < b) v += g_blocksums[lane];
        int l2 = lane + 32;
        if (l2 < nb && l2 < b) v += g_blocksums[l2];
        #pragma unroll
        for (int off = 16; off; off >>= 1)
            v += __shfl_xor_sync(0xffffffffu, v, off);
        if (lane == 0) s_off = v;
    }
    __syncthreads();
    int i = b * 1024 + threadIdx.x;
    if (i < n) {
        int r = g_rowstart[i] + s_off;
        g_rowstart[i] = r;
        g_cursor[i] = r;
    }
    if (b == nb - 1 && threadIdx.x == 0)
        g_rowstart[n] = s_off + g_blocksums[b];
}

__global__ void fill_kernel(int E) {
    int e = blockIdx.x * blockDim.x + threadIdx.x;
    if (e >= E) return;
    int pos = atomicAdd(&g_cursor[g_dst[e]], 1);
    g_csr[pos] = g_src[e];
}

// ---------------- layer-1 aggregation: warp per node, fp16 gather + fp16 out ----------------
__global__ void agg1_kernel(int n) {
    int w = (blockIdx.x * blockDim.x + threadIdx.x) >> 5;
    int lane = threadIdx.x & 31;
    if (w >= n) return;
    int s0 = g_rowstart[w], s1 = g_rowstart[w + 1];
    float f0 = 0.f, f1 = 0.f, f2 = 0.f, f3 = 0.f;
    float f4 = 0.f, f5 = 0.f, f6 = 0.f, f7 = 0.f;
    for (int e = s0; e < s1; e++) {
        int s = g_csr[e];
        uint4 v = *(const uint4*)(g_xhalf + (size_t)s * C + 8 * lane);
        float2 p0 = __half22float2(*(__half2*)&v.x);
        float2 p1 = __half22float2(*(__half2*)&v.y);
        float2 p2 = __half22float2(*(__half2*)&v.z);
        float2 p3 = __half22float2(*(__half2*)&v.w);
        f0 += p0.x; f1 += p0.y; f2 += p1.x; f3 += p1.y;
        f4 += p2.x; f5 += p2.y; f6 += p3.x; f7 += p3.y;
    }
    float inv = (s1 > s0) ? 1.f / (float)(s1 - s0) : 0.f;
    f0 *= inv; f1 *= inv; f2 *= inv; f3 *= inv;
    f4 *= inv; f5 *= inv; f6 *= inv; f7 *= inv;
    *(uint4*)(g_agghalf + (size_t)w * C + 8 * lane) =
        make_uint4(packhf(f0, f1), packhf(f2, f3), packhf(f4, f5), packhf(f6, f7));
}

// ---------------- double-buffered single-term fp16 mma GEMM + fused pq epilogue ----------------
// CTA: 128 rows x 256 cols, 512 threads, warp grid 4m x 4n, warp tile 32x64.
// D = A * W (both fp16), fp32 accum. K=512, 16 tiles of 32. 2-stage cp.async.
#define PA 40                        // smem pitch in halfs (80 bytes)
#define SA 0                         // 128*80 = 10240
#define SB 10240                     // 256*80 = 20480
#define STAGE 30720
#define SW2   61440                  // 256*16 = 4096
#define SB1   65536                  // 1024
#define SMEMT 66560

__global__ void __launch_bounds__(512, 1) gemm_mma_kernel(
    const float* __restrict__ b1, const float* __restrict__ b2, int M)
{
    extern __shared__ __align__(16) char smem[];
    u32 sb = smem_u32(smem);
    int tid = threadIdx.x;
    int lane = tid & 31, wid = tid >> 5;
    int wm = wid >> 2, wn = wid & 3;
    int m0 = blockIdx.x * 128;

    float4* s_w2 = (float4*)(smem + SW2);
    float*  s_b1 = (float*)(smem + SB1);
    if (tid < 256) {
        s_w2[tid] = g_W2pack[tid];
        s_b1[tid] = b1[tid];
    }

    // per-thread cp.async assignments: A = 512 x 16B chunks, B = 1024 x 16B chunks
    int arow = tid >> 2, ach = tid & 3;
    int am = m0 + arow;
    u32 asz = (am < M) ? 16u : 0u;
    u32 a_soff = (u32)(arow * 80 + ach * 16);
    size_t a_goff = (size_t)am * C + ach * 8;

    auto issue = [&](int kt, int st) {
        u32 s0 = sb + st * STAGE;
        const __half* asrc = (kt < 8) ? g_agghalf : g_xhalf;
        size_t ago = a_goff + (size_t)(kt & 7) * 32;
        CP16(s0 + SA + a_soff, asrc + ago, asz);
        int kg = kt * 32;
        #pragma unroll
        for (int i = 0; i < 2; i++) {
            int t = tid + i * 512;
            int nr = t >> 2, ch = t & 3;
            CP16(s0 + SB + (u32)(nr * 80 + ch * 16),
                 g_Whalf + (size_t)nr * 512 + kg + ch * 8, 16u);
        }
        CP_COMMIT();
    };

    float c[2][8][4];
    #pragma unroll
    for (int mi = 0; mi < 2; mi++)
        #pragma unroll
        for (int ni = 0; ni < 8; ni++)
            #pragma unroll
            for (int j = 0; j < 4; j++) c[mi][ni][j] = 0.f;

    int ra = lane >> 2;
    int ka2 = (lane & 3) * 2;

    issue(0, 0);
    for (int kt = 0; kt < 16; kt++) {
        if (kt < 15) { issue(kt + 1, (kt + 1) & 1); CP_WAIT(1); }
        else         { CP_WAIT(0); }
        __syncthreads();
        char* sB = smem + (kt & 1) * STAGE;
        #pragma unroll
        for (int k16 = 0; k16 < 2; k16++) {
            int k0 = k16 * 16;
            u32 a[2][4];
            #pragma unroll
            for (int mi = 0; mi < 2; mi++) {
                int base = ((32 * wm + 16 * mi + ra) * PA + k0 + ka2) * 2;
                a[mi][0] = *(u32*)(sB + SA + base);
                a[mi][1] = *(u32*)(sB + SA + base + 8 * PA * 2);
                a[mi][2] = *(u32*)(sB + SA + base + 16);
                a[mi][3] = *(u32*)(sB + SA + base + 8 * PA * 2 + 16);
            }
            u32 bh[8][2];
            #pragma unroll
            for (int ni = 0; ni < 8; ni++) {
                int nb = 64 * wn + 8 * ni + ra;
                int boff = (nb * PA + k0 + ka2) * 2;
                bh[ni][0] = *(u32*)(sB + SB + boff);
                bh[ni][1] = *(u32*)(sB + SB + boff + 16);
            }
            #pragma unroll
            for (int mi = 0; mi < 2; mi++)
                #pragma unroll
                for (int ni = 0; ni < 8; ni++)
                    mma16816(c[mi][ni], a[mi], bh[ni]);
        }
        __syncthreads();
    }

    // ---- epilogue: h = relu(acc + b1); fused p,q projection
    float pp[2][2][4];
    #pragma unroll
    for (int mi = 0; mi < 2; mi++)
        #pragma unroll
        for (int hh = 0; hh < 2; hh++)
            #pragma unroll
            for (int r = 0; r < 4; r++) pp[mi][hh][r] = 0.f;
    #pragma unroll
    for (int mi = 0; mi < 2; mi++)
        #pragma unroll
        for (int ni = 0; ni < 8; ni++)
            #pragma unroll
            for (int j = 0; j < 4; j++) {
                int col = 64 * wn + 8 * ni + ka2 + (j & 1);
                float h = fmaxf(c[mi][ni][j] + s_b1[col], 0.f);
                float4 wv = s_w2[col];
                int hh = j >> 1;
                pp[mi][hh][0] = fmaf(h, wv.x, pp[mi][hh][0]);
                pp[mi][hh][1] = fmaf(h, wv.y, pp[mi][hh][1]);
                pp[mi][hh][2] = fmaf(h, wv.z, pp[mi][hh][2]);
                pp[mi][hh][3] = fmaf(h, wv.w, pp[mi][hh][3]);
            }
    #pragma unroll
    for (int mi = 0; mi < 2; mi++)
        #pragma unroll
        for (int hh = 0; hh < 2; hh++)
            #pragma unroll
            for (int r = 0; r < 4; r++) {
                float v = pp[mi][hh][r];
                v += __shfl_xor_sync(0xffffffffu, v, 1);
                v += __shfl_xor_sync(0xffffffffu, v, 2);
                pp[mi][hh][r] = v;
            }
    float* s_part = (float*)smem;   // [4 wn][128 row][4]
    if ((lane & 3) == 0) {
        #pragma unroll
        for (int mi = 0; mi < 2; mi++)
            #pragma unroll
            for (int hh = 0; hh < 2; hh++) {
                int row = 32 * wm + 16 * mi + 8 * hh + ra;
                *(float4*)&s_part[(wn * 128 + row) * 4] =
                    make_float4(pp[mi][hh][0], pp[mi][hh][1], pp[mi][hh][2], pp[mi][hh][3]);
            }
    }
    __syncthreads();
    if (tid < 128) {
        int m = m0 + tid;
        if (m < M) {
            float4 s = make_float4(0.f, 0.f, 0.f, 0.f);
            #pragma unroll
            for (int w = 0; w < 4; w++) {
                float4 v = *(float4*)&s_part[(w * 128 + tid) * 4];
                s.x += v.x; s.y += v.y; s.z += v.z; s.w += v.w;
            }
            *(float4*)&g_pq[m * 4] = make_float4(s.x, s.y, s.z + b2[0], s.w + b2[1]);
        }
    }
}

// ---------------- layer-2 aggregation + log_softmax ----------------
__global__ void final_kernel(float* __restrict__ out, int n) {
    int i = blockIdx.x * blockDim.x + threadIdx.x;
    if (i >= n) return;
    int s0 = g_rowstart[i], s1 = g_rowstart[i + 1];
    float p0 = 0.f, p1 = 0.f;
    for (int e = s0; e < s1; e++) {
        int s = g_csr[e];
        p0 += g_pq[s * 4 + 0];
        p1 += g_pq[s * 4 + 1];
    }
    float inv = (s1 > s0) ? 1.f / (float)(s1 - s0) : 0.f;
    float o0 = p0 * inv + g_pq[i * 4 + 2];
    float o1 = p1 * inv + g_pq[i * 4 + 3];
    float m = fmaxf(o0, o1);
    float l = m + log1pf(expf(fminf(o0, o1) - m));
    out[i * 2 + 0] = o0 - l;
    out[i * 2 + 1] = o1 - l;
}

// ---------------- launcher ----------------
extern "C" void kernel_launch(void* const* d_in, const int* in_sizes, int n_in,
                              void* d_out, int out_size) {
    const float* x   = (const float*)d_in[0];
    const int*   ei  = (const int*)d_in[1];
    const float* W1l = (const float*)d_in[2];
    const float* b1  = (const float*)d_in[3];
    const float* W1r = (const float*)d_in[4];
    const float* W2l = (const float*)d_in[5];
    const float* b2  = (const float*)d_in[6];
    const float* W2r = (const float*)d_in[7];
    float* out = (float*)d_out;

    int n = in_sizes[0] / C;  if (n > NMAX) n = NMAX;
    int E = in_sizes[1] / 2;  if (E > EMAX) E = EMAX;
    int nb = (n + 1023) / 1024;
    int nbx = (n * 64 + 255) / 256;
    int nbc = (E + 255) / 256;

    cudaFuncSetAttribute(gemm_mma_kernel, cudaFuncAttributeMaxDynamicSharedMemorySize,
                         SMEMT);

    init_kernel<<<(n + 255) / 256, 256>>>((const unsigned*)ei, n);
    prep_kernel<<<nbx + nbc + 512, 256>>>(x, ei, W1l, W1r, W2l, W2r, n, E, nbx, nbc);
    scan_block_kernel<<<nb, 1024>>>(n);
    scan_add_kernel<<<nb, 1024>>>(n, nb);
    fill_kernel<<<(E + 255) / 256, 256>>>(E);
    agg1_kernel<<<(n * 32 + 255) / 256, 256>>>(n);
    gemm_mma_kernel<<<(n + 127) / 128, 512, SMEMT>>>(b1, b2, n);
    final_kernel<<<(n + 255) / 256, 256>>>(out, n);
}